// round 15
// baseline (speedup 1.0000x reference)
#include <cuda_runtime.h>
#include <cstdint>

#define BB    4
#define LL    1024
#define DIMM  512
#define NH    8
#define HDIM  64
#define KNEED 716          // max(1, int(1024 * 0.7))
#define NEGV  (-1e9f)

typedef unsigned long long ull;

// ---------------- scratch (static device globals; no allocation) ----------------
__device__ float g_q [BB*NH*LL*HDIM];   // (b,h,i,d)   NOTE: pre-scaled by 0.125
__device__ float g_kt[BB*NH*HDIM*LL];   // (b,h,d,j)  transposed K
__device__ float g_v [BB*NH*LL*HDIM];   // (b,h,j,d)
__device__ float g_ao[BB*LL*DIMM];      // (b,i,h*64+d) attention output
__device__ float g_pw[BB*3];            // pattern weights per batch
__device__ float g_sc[BB*NH*LL*LL];     // 134MB normalized-P buffer

// ---------------- f32x2 packed helpers ----------------
__device__ __forceinline__ ull pk2(float a, float b) {
    ull r; asm("mov.b64 %0,{%1,%2};" : "=l"(r) : "f"(a), "f"(b)); return r;
}
__device__ __forceinline__ void fma2(ull& d, ull a, ull b) {
    asm("fma.rn.f32x2 %0, %1, %2, %0;" : "+l"(d) : "l"(a), "l"(b));
}
__device__ __forceinline__ ull mul2(ull a, ull b) {
    ull r; asm("mul.rn.f32x2 %0, %1, %2;" : "=l"(r) : "l"(a), "l"(b)); return r;
}
__device__ __forceinline__ ull add2(ull a, ull b) {
    ull r; asm("add.rn.f32x2 %0, %1, %2;" : "=l"(r) : "l"(a), "l"(b)); return r;
}
__device__ __forceinline__ float2 upk(ull v) {
    float2 r; asm("mov.b64 {%0,%1},%2;" : "=f"(r.x), "=f"(r.y) : "l"(v)); return r;
}
__device__ __forceinline__ unsigned ordkey(float s) {
    unsigned u = __float_as_uint(s);
    return (u & 0x80000000u) ? ~u : (u | 0x80000000u);
}

// ======================= K1: 128x128x16 GEMM, B-reinterpret + A-side pk2 (scoreg pattern) ======
template<int MODE>
__global__ void __launch_bounds__(256, 2) gemm128(const float* __restrict__ A,
                                                  const float* __restrict__ W,
                                                  const float* __restrict__ bias,
                                                  float* __restrict__ out) {
    __shared__ float As[2][16][132];
    __shared__ float Bs[2][16][132];    // row 528B = 33*16 -> 16B-aligned rows
    const int m0 = blockIdx.y * 128, n0 = blockIdx.x * 128;
    const int tid = threadIdx.x;
    const int tx = tid & 15, ty = tid >> 4;
    const float* Ap = (MODE == 1) ? g_ao : A;

    ull acc[8][4];
    #pragma unroll
    for (int r = 0; r < 8; r++)
        #pragma unroll
        for (int c = 0; c < 4; c++) acc[r][c] = 0ull;

    float4 pa[2], pb[2];
    auto ldT = [&](int kt) {
        const int k0 = kt * 16;
        #pragma unroll
        for (int i = 0; i < 2; i++) {
            int idx = tid + i * 256;
            int r = idx >> 2, kq = (idx & 3) * 4;
            pa[i] = *(const float4*)(Ap + (size_t)(m0 + r) * 512 + k0 + kq);
            pb[i] = *(const float4*)(W  + (size_t)(n0 + r) * 512 + k0 + kq);
        }
    };
    auto stT = [&](int s) {
        #pragma unroll
        for (int i = 0; i < 2; i++) {
            int idx = tid + i * 256;
            int r = idx >> 2, kq = (idx & 3) * 4;
            As[s][kq+0][r] = pa[i].x; As[s][kq+1][r] = pa[i].y;
            As[s][kq+2][r] = pa[i].z; As[s][kq+3][r] = pa[i].w;
            Bs[s][kq+0][r] = pb[i].x; Bs[s][kq+1][r] = pb[i].y;
            Bs[s][kq+2][r] = pb[i].z; Bs[s][kq+3][r] = pb[i].w;
        }
    };

    ldT(0); stT(0); __syncthreads();
    ldT(1);

    for (int kt = 0; kt < 32; kt++) {
        if (kt < 31) stT((kt + 1) & 1);
        if (kt < 30) ldT(kt + 2);
        const int st = kt & 1;
        #pragma unroll
        for (int kk = 0; kk < 16; kk++) {
            ulonglong2 b0 = *(const ulonglong2*)&Bs[st][kk][tx * 4];       // packed (n,n+1),(n+2,n+3)
            ulonglong2 b1 = *(const ulonglong2*)&Bs[st][kk][64 + tx * 4];
            float4 av0 = *(const float4*)&As[st][kk][ty * 8];
            float4 av1 = *(const float4*)&As[st][kk][ty * 8 + 4];
            float am[8] = {av0.x, av0.y, av0.z, av0.w, av1.x, av1.y, av1.z, av1.w};
            #pragma unroll
            for (int r = 0; r < 8; r++) {
                ull ab = pk2(am[r], am[r]);
                fma2(acc[r][0], ab, b0.x); fma2(acc[r][1], ab, b0.y);
                fma2(acc[r][2], ab, b1.x); fma2(acc[r][3], ab, b1.y);
            }
        }
        if (kt < 31) __syncthreads();
    }

    #pragma unroll
    for (int r = 0; r < 8; r++) {
        int m = m0 + ty * 8 + r;
        #pragma unroll
        for (int c = 0; c < 4; c++) {
            int n = n0 + ((c < 2) ? (tx * 4 + 2 * c) : (64 + tx * 4 + 2 * (c - 2)));
            if (MODE == 0) {
                int b = m >> 10, i = m & 1023;
                float2 v = upk(acc[r][c]);
                if (n < 512) {
                    int hh = n >> 6, d = n & 63;
                    float* p = g_q + (((size_t)(b * 8 + hh) << 10) + i) * 64 + d;
                    p[0] = v.x * 0.125f; p[1] = v.y * 0.125f;   // fold attn scale (exact pow2)
                } else if (n < 1024) {
                    int nn = n - 512, hh = nn >> 6, d = nn & 63;
                    float* p = g_kt + ((size_t)(b * 8 + hh) * 64 + d) * 1024 + i;
                    p[0] = v.x; p[1024] = v.y;
                } else {
                    int nn = n - 1024, hh = nn >> 6, d = nn & 63;
                    float* p = g_v + (((size_t)(b * 8 + hh) << 10) + i) * 64 + d;
                    p[0] = v.x; p[1] = v.y;
                }
            } else {
                ull bv = *(const ull*)(bias + n);
                *(ull*)(out + (size_t)m * 512 + n) = add2(acc[r][c], bv);
            }
        }
    }
}

// ======================= K2: fused pooling + selector (4 blocks, 512 thr) =======================
__global__ void __launch_bounds__(512) selector2(const float* __restrict__ x,
                                                 const float* __restrict__ W1,
                                                 const float* __restrict__ b1,
                                                 const float* __restrict__ W2,
                                                 const float* __restrict__ b2,
                                                 const float* __restrict__ logtau) {
    __shared__ float part[4][512];     // row-group partial sums
    __shared__ float pooled[512];
    __shared__ float hh[256];
    __shared__ float lg[3];
    const int b = blockIdx.x, tid = threadIdx.x;
    const float* xb = x + (size_t)b * 1024 * 512;
    {
        const int rg = tid >> 7, c4 = (tid & 127) * 4;   // 4 row-groups x 128 col-quads
        float4 s = {0.f, 0.f, 0.f, 0.f};
        #pragma unroll 8
        for (int r = rg; r < 1024; r += 4) {
            float4 v = *(const float4*)(xb + (size_t)r * 512 + c4);
            s.x += v.x; s.y += v.y; s.z += v.z; s.w += v.w;
        }
        *(float4*)&part[rg][c4] = s;
    }
    __syncthreads();
    pooled[tid] = (part[0][tid] + part[1][tid] + part[2][tid] + part[3][tid]) * (1.0f / 1024.0f);
    __syncthreads();
    if (tid < 256) {
        float a = b1[tid];
        const float* wr = W1 + (size_t)tid * 512;
        #pragma unroll 4
        for (int d = 0; d < 512; d++) a = fmaf(pooled[d], wr[d], a);
        hh[tid] = a > 0.f ? a : 0.f;
    }
    __syncthreads();
    if (tid < 3) {
        float a = b2[tid];
        const float* wr = W2 + (size_t)tid * 256;
        for (int d = 0; d < 256; d++) a = fmaf(hh[d], wr[d], a);
        lg[tid] = a;
    }
    __syncthreads();
    if (tid == 0) {
        float tau = expf(logtau[0]);
        tau = fminf(fmaxf(tau, 1e-4f), 10.0f);
        float l0 = lg[0] / tau, l1 = lg[1] / tau, l2 = lg[2] / tau;
        float mx = fmaxf(l0, fmaxf(l1, l2));
        float e0 = expf(l0 - mx), e1 = expf(l1 - mx), e2 = expf(l2 - mx);
        float inv = 1.0f / (e0 + e1 + e2);
        g_pw[b * 3 + 0] = e0 * inv;
        g_pw[b * 3 + 1] = e1 * inv;
        g_pw[b * 3 + 2] = e2 * inv;
    }
}

// ======================= K3: score GEMM, whole K=64 resident, 1 barrier (R7-proven) ============
struct SmemSG {
    float4 As4[16][130];   // [kq4][row]: component e = Q[row][kq4*4+e]; 33.3 KB
    float  Bs[64][132];    // [kk][col]; 33.8 KB
};

__global__ void __launch_bounds__(256, 2) scoreg() {
    extern __shared__ char smraw[];
    SmemSG* sm = (SmemSG*)smraw;
    const int bh = blockIdx.z;
    const int m0 = blockIdx.y * 128, n0 = blockIdx.x * 128;
    const int tid = threadIdx.x;
    const int tx = tid & 15, ty = tid >> 4;
    const float* qg  = g_q  + (size_t)bh * 65536;
    const float* ktg = g_kt + (size_t)bh * 65536;

    #pragma unroll
    for (int it = 0; it < 8; it++) {
        int idx = tid + it * 256;
        int row = idx >> 4, kq4 = idx & 15;
        sm->As4[kq4][row] = *(const float4*)(qg + (size_t)(m0 + row) * 64 + kq4 * 4);
    }
    #pragma unroll
    for (int it = 0; it < 8; it++) {
        int idx = tid + it * 256;
        int kk = idx >> 5, c4 = idx & 31;
        *(float4*)&sm->Bs[kk][c4 * 4] = *(const float4*)(ktg + (size_t)kk * 1024 + n0 + c4 * 4);
    }
    __syncthreads();

    ull acc[8][4];
    #pragma unroll
    for (int r = 0; r < 8; r++)
        #pragma unroll
        for (int c = 0; c < 4; c++) acc[r][c] = 0ull;

    #pragma unroll
    for (int kq4 = 0; kq4 < 16; kq4++) {
        float4 a[8];
        #pragma unroll
        for (int r = 0; r < 8; r++) a[r] = sm->As4[kq4][ty * 8 + r];
        #pragma unroll
        for (int e = 0; e < 4; e++) {
            const int kk = kq4 * 4 + e;
            ulonglong2 b0 = *(const ulonglong2*)&sm->Bs[kk][tx * 4];
            ulonglong2 b1 = *(const ulonglong2*)&sm->Bs[kk][64 + tx * 4];
            #pragma unroll
            for (int r = 0; r < 8; r++) {
                float av = (e == 0) ? a[r].x : (e == 1) ? a[r].y : (e == 2) ? a[r].z : a[r].w;
                ull ab = pk2(av, av);
                fma2(acc[r][0], ab, b0.x); fma2(acc[r][1], ab, b0.y);
                fma2(acc[r][2], ab, b1.x); fma2(acc[r][3], ab, b1.y);
            }
        }
    }

    #pragma unroll
    for (int r = 0; r < 8; r++) {
        size_t rowp = ((size_t)bh << 20) + (size_t)(m0 + ty * 8 + r) * 1024;
        float2 v0 = upk(acc[r][0]);
        float2 v1 = upk(acc[r][1]);
        float4 o0 = {v0.x, v0.y, v1.x, v1.y};
        *(float4*)(g_sc + rowp + n0 + tx * 4) = o0;
        float2 v2 = upk(acc[r][2]);
        float2 v3 = upk(acc[r][3]);
        float4 o1 = {v2.x, v2.y, v3.x, v3.y};
        *(float4*)(g_sc + rowp + n0 + 64 + tx * 4) = o1;
    }
}

// ======================= K4: mask + topk + softmax (pre-normalized P); 1 warp = 1 row ==========
__global__ void __launch_bounds__(512) masksm(const int* __restrict__ mask,
                                              const float* __restrict__ sparse_w,
                                              const float* __restrict__ sparse_b) {
    __shared__ unsigned hist[16][256];
    const int tid = threadIdx.x;
    const int wq = tid >> 5, lane = tid & 31;
    const int i0 = blockIdx.x * 16;
    const int h  = blockIdx.y;
    const int b  = blockIdx.z;
    const int bh = b * 8 + h;
    float* rowp = g_sc + ((size_t)bh << 20) + (size_t)(i0 + wq) * 1024;

    const float pw0 = g_pw[b * 3 + 0], pw1 = g_pw[b * 3 + 1], pw2 = g_pw[b * 3 + 2];
    const float wsp = sparse_w[h], bsp = sparse_b[h];
    const bool need_smask = (((pw1 > 0.05f) != (pw1 + pw2 > 0.05f)) ||
                             ((pw0 + pw1 > 0.05f) != (pw0 + pw1 + pw2 > 0.05f)));

    float4 v[8];
    #pragma unroll
    for (int t = 0; t < 8; t++) v[t] = *(const float4*)(rowp + t * 128 + lane * 4);

    unsigned thrv = 0;
    if (need_smask) {
        unsigned prefix = 0;
        int kneed = KNEED;
        #pragma unroll
        for (int pass = 0; pass < 4; pass++) {
            const int shift = 24 - 8 * pass;
            #pragma unroll
            for (int q = 0; q < 8; q++) hist[wq][lane * 8 + q] = 0u;
            __syncwarp();
            #pragma unroll
            for (int t = 0; t < 8; t++) {
                float fv[4] = {v[t].x, v[t].y, v[t].z, v[t].w};
                #pragma unroll
                for (int e = 0; e < 4; e++) {
                    float s = fmaf(fv[e], wsp, bsp);
                    unsigned u = ordkey(s);
                    bool cand = (pass == 0) || (((u ^ prefix) >> (shift + 8)) == 0u);
                    int bucket = cand ? (int)((u >> shift) & 255u) : 256;
                    unsigned mm = __match_any_sync(0xffffffffu, bucket);
                    if ((__ffs(mm) - 1) == lane && bucket < 256)
                        atomicAdd(&hist[wq][bucket], (unsigned)__popc(mm));
                }
            }
            __syncwarp();
            const int base = 255 - lane * 8;
            int c[8]; int loc = 0;
            #pragma unroll
            for (int q = 0; q < 8; q++) { c[q] = (int)hist[wq][base - q]; loc += c[q]; }
            int pre = loc;
            #pragma unroll
            for (int o = 1; o < 32; o <<= 1) {
                int vv = __shfl_up_sync(0xffffffffu, pre, o);
                if (lane >= o) pre += vv;
            }
            const int excl = pre - loc;
            const bool hit = (excl < kneed) && (kneed <= pre);
            const unsigned hb = __ballot_sync(0xffffffffu, hit);
            const int hl = __ffs(hb) - 1;
            int bsel = 0, kn2 = 0;
            if (hit) {
                int rem = kneed - excl;
                #pragma unroll
                for (int q = 0; q < 8; q++) {
                    if (rem <= c[q]) { bsel = base - q; kn2 = rem; break; }
                    rem -= c[q];
                }
            }
            bsel = __shfl_sync(0xffffffffu, bsel, hl);
            kn2  = __shfl_sync(0xffffffffu, kn2,  hl);
            prefix |= ((unsigned)bsel) << shift;
            kneed = kn2;
            __syncwarp();
        }
        thrv = prefix;
    }

    const int* mrow = mask + b * 1024;
    const int ii = i0 + wq;
    float locmax = -3.0e38f;
    int any = 0;
    #pragma unroll
    for (int t = 0; t < 8; t++) {
        int4 mm4 = *(const int4*)(mrow + t * 128 + lane * 4);
        float fv[4] = {v[t].x, v[t].y, v[t].z, v[t].w};
        int   mv[4] = {mm4.x, mm4.y, mm4.z, mm4.w};
        #pragma unroll
        for (int e = 0; e < 4; e++) {
            int j = t * 128 + lane * 4 + e;
            float s = fmaf(fv[e], wsp, bsp);
            float smv = (ordkey(s) >= thrv) ? 1.0f : 0.0f;
            float lcl = (j >= ii - 16 && j <= ii + 16) ? 1.0f : 0.0f;
            float comb = fmaf(pw0, lcl, fmaf(pw2, smv, pw1));
            bool keep = (comb > 0.05f) && (mv[e] != 0);
            if (keep) { locmax = fmaxf(locmax, fv[e]); any = 1; }
            else      fv[e] = NEGV;
        }
        v[t].x = fv[0]; v[t].y = fv[1]; v[t].z = fv[2]; v[t].w = fv[3];
    }
    #pragma unroll
    for (int o = 16; o; o >>= 1) {
        locmax = fmaxf(locmax, __shfl_xor_sync(0xffffffffu, locmax, o));
        any   |= __shfl_xor_sync(0xffffffffu, any, o);
    }
    if (!any) {
        if (lane == 0) v[0].x = 0.0f;    // j==0 fallback
        locmax = 0.0f;
    }

    float lsum = 0.f;
    #pragma unroll
    for (int t = 0; t < 8; t++) {
        v[t].x = __expf(v[t].x - locmax); v[t].y = __expf(v[t].y - locmax);
        v[t].z = __expf(v[t].z - locmax); v[t].w = __expf(v[t].w - locmax);
        lsum += (v[t].x + v[t].y) + (v[t].z + v[t].w);
    }
    #pragma unroll
    for (int o = 16; o; o >>= 1)
        lsum += __shfl_xor_sync(0xffffffffu, lsum, o);
    const float inv = 1.0f / lsum;
    #pragma unroll
    for (int t = 0; t < 8; t++) {
        v[t].x *= inv; v[t].y *= inv; v[t].z *= inv; v[t].w *= inv;
        *(float4*)(rowp + t * 128 + lane * 4) = v[t];
    }
}

// ======================= K5: AV GEMM, 64x64 tile, 4r x 8c, ratio-4, single-sync (R9) ===========
__global__ void __launch_bounds__(128, 4) avg_kernel() {
    __shared__ ull   Ps2[2][32][66];   // [kk][row] dup pairs; 33.8 KB
    __shared__ float Bs [2][32][68];   // [kk][col]; 17.4 KB
    const int bh = blockIdx.y;
    const int m0 = blockIdx.x * 64;
    const int tid = threadIdx.x;
    const int tx = tid & 7, ty = tid >> 3;   // ty 0..15: rows ty*4..+4; cols tx*4 and 32+tx*4
    const float* pg = g_sc + ((size_t)bh << 20);
    const float* vg = g_v + (size_t)bh * 65536;

    ull acc[4][4];
    #pragma unroll
    for (int r = 0; r < 4; r++)
        #pragma unroll
        for (int c = 0; c < 4; c++) acc[r][c] = 0ull;

    float4 pr[4], vr[4];
    auto ldT = [&](int c) {
        const int k0 = c * 32;
        #pragma unroll
        for (int it = 0; it < 4; it++) {
            int idx = tid + it * 128;   // 0..511
            pr[it] = *(const float4*)(pg + (size_t)(m0 + (idx >> 3)) * 1024 + k0 + (idx & 7) * 4);
            vr[it] = *(const float4*)(vg + (size_t)(k0 + (idx >> 4)) * 64 + (idx & 15) * 4);
        }
    };
    auto stT = [&](int s) {
        #pragma unroll
        for (int it = 0; it < 4; it++) {
            int idx = tid + it * 128;
            int row = idx >> 3, kq4 = idx & 7;
            Ps2[s][kq4 * 4 + 0][row] = pk2(pr[it].x, pr[it].x);
            Ps2[s][kq4 * 4 + 1][row] = pk2(pr[it].y, pr[it].y);
            Ps2[s][kq4 * 4 + 2][row] = pk2(pr[it].z, pr[it].z);
            Ps2[s][kq4 * 4 + 3][row] = pk2(pr[it].w, pr[it].w);
            *(float4*)&Bs[s][idx >> 4][(idx & 15) * 4] = vr[it];
        }
    };

    ldT(0); stT(0); __syncthreads();
    ldT(1);

    for (int c = 0; c < 32; c++) {
        if (c < 31) stT((c + 1) & 1);
        if (c < 30) ldT(c + 2);
        const int st = c & 1;
        #pragma unroll
        for (int kk = 0; kk < 32; kk++) {
            ulonglong2 p01 = *(const ulonglong2*)&Ps2[st][kk][ty * 4];
            ulonglong2 p23 = *(const ulonglong2*)&Ps2[st][kk][ty * 4 + 2];
            ulonglong2 b0  = *(const ulonglong2*)&Bs[st][kk][tx * 4];
            ulonglong2 b1  = *(const ulonglong2*)&Bs[st][kk][32 + tx * 4];
            ull p[4] = {p01.x, p01.y, p23.x, p23.y};
            #pragma unroll
            for (int r = 0; r < 4; r++) {
                fma2(acc[r][0], p[r], b0.x); fma2(acc[r][1], p[r], b0.y);
                fma2(acc[r][2], p[r], b1.x); fma2(acc[r][3], p[r], b1.y);
            }
        }
        if (c < 31) __syncthreads();
    }

    const int b = bh >> 3, h = bh & 7;
    #pragma unroll
    for (int r = 0; r < 4; r++) {
        int i = m0 + ty * 4 + r;
        float* op = g_ao + ((size_t)(b * 1024 + i)) * 512 + h * 64;
        float2 c0 = upk(acc[r][0]);
        float2 c1 = upk(acc[r][1]);
        float4 o0 = {c0.x, c0.y, c1.x, c1.y};
        *(float4*)(op + tx * 4) = o0;
        float2 c2 = upk(acc[r][2]);
        float2 c3 = upk(acc[r][3]);
        float4 o1 = {c2.x, c2.y, c3.x, c3.y};
        *(float4*)(op + 32 + tx * 4) = o1;
    }
}

// ======================= launch =======================
// Order: selector2, qkv, scoreg, masksm, avg, proj.
// ncu captures overall launch #6 (2 harness pre-launches + "-s 5"); with the
// fused selector that slot lands on masksm — previously unprofiled.
extern "C" void kernel_launch(void* const* d_in, const int* in_sizes, int n_in,
                              void* d_out, int out_size) {
    const float* x      = (const float*)d_in[0];
    const int*   mask   = (const int*)  d_in[1];
    const float* Wqkv   = (const float*)d_in[2];
    const float* Wproj  = (const float*)d_in[3];
    const float* bproj  = (const float*)d_in[4];
    const float* Wsel1  = (const float*)d_in[5];
    const float* bsel1  = (const float*)d_in[6];
    const float* Wsel2  = (const float*)d_in[7];
    const float* bsel2  = (const float*)d_in[8];
    const float* logtau = (const float*)d_in[9];
    const float* sw     = (const float*)d_in[10];
    const float* sb     = (const float*)d_in[11];
    float* out = (float*)d_out;

    static int smem_set = 0;
    if (!smem_set) {
        cudaFuncSetAttribute(scoreg, cudaFuncAttributeMaxDynamicSharedMemorySize,
                             (int)sizeof(SmemSG));
        smem_set = 1;
    }

    selector2<<<4, 512>>>(x, Wsel1, bsel1, Wsel2, bsel2, logtau);
    gemm128<0><<<dim3(12, 32), 256>>>(x, Wqkv, nullptr, nullptr);
    scoreg<<<dim3(8, 8, 32), 256, sizeof(SmemSG)>>>();
    masksm<<<dim3(64, 8, 4), 512>>>(mask, sw, sb);
    avg_kernel<<<dim3(16, 32), 128>>>();
    gemm128<1><<<dim3(4, 32), 256>>>(nullptr, Wproj, bproj, out);
}

// round 16
// speedup vs baseline: 1.0812x; 1.0812x over previous
#include <cuda_runtime.h>
#include <cstdint>

#define BB    4
#define LL    1024
#define DIMM  512
#define NH    8
#define HDIM  64
#define KNEED 716          // max(1, int(1024 * 0.7))
#define NEGV  (-1e9f)

typedef unsigned long long ull;

// ---------------- scratch (static device globals; no allocation) ----------------
__device__ float g_q [BB*NH*LL*HDIM];   // (b,h,i,d)   NOTE: pre-scaled by 0.125
__device__ float g_kt[BB*NH*HDIM*LL];   // (b,h,d,j)  transposed K
__device__ float g_v [BB*NH*LL*HDIM];   // (b,h,j,d)
__device__ float g_ao[BB*LL*DIMM];      // (b,i,h*64+d) attention output
__device__ float g_pw[BB*3];            // pattern weights per batch
__device__ float g_part[BB*8*DIMM];     // pooling partials
__device__ float g_sc[BB*NH*LL*LL];     // 134MB normalized-P buffer

// ---------------- f32x2 packed helpers ----------------
__device__ __forceinline__ ull pk2(float a, float b) {
    ull r; asm("mov.b64 %0,{%1,%2};" : "=l"(r) : "f"(a), "f"(b)); return r;
}
__device__ __forceinline__ void fma2(ull& d, ull a, ull b) {
    asm("fma.rn.f32x2 %0, %1, %2, %0;" : "+l"(d) : "l"(a), "l"(b));
}
__device__ __forceinline__ ull mul2(ull a, ull b) {
    ull r; asm("mul.rn.f32x2 %0, %1, %2;" : "=l"(r) : "l"(a), "l"(b)); return r;
}
__device__ __forceinline__ ull add2(ull a, ull b) {
    ull r; asm("add.rn.f32x2 %0, %1, %2;" : "=l"(r) : "l"(a), "l"(b)); return r;
}
__device__ __forceinline__ float2 upk(ull v) {
    float2 r; asm("mov.b64 {%0,%1},%2;" : "=f"(r.x), "=f"(r.y) : "l"(v)); return r;
}
__device__ __forceinline__ unsigned ordkey(float s) {
    unsigned u = __float_as_uint(s);
    return (u & 0x80000000u) ? ~u : (u | 0x80000000u);
}

// ======================= K1: 128x128x16 GEMM, single-sync ping-pong (R9-proven, exact) =========
template<int MODE>
__global__ void __launch_bounds__(256, 2) gemm128(const float* __restrict__ A,
                                                  const float* __restrict__ W,
                                                  const float* __restrict__ bias,
                                                  float* __restrict__ out) {
    __shared__ float As[2][16][132];
    __shared__ float Bs[2][16][132];
    const int m0 = blockIdx.y * 128, n0 = blockIdx.x * 128;
    const int tid = threadIdx.x;
    const int tx = tid & 15, ty = tid >> 4;
    const float* Ap = (MODE == 1) ? g_ao : A;

    ull acc[8][4];
    #pragma unroll
    for (int r = 0; r < 8; r++)
        #pragma unroll
        for (int c = 0; c < 4; c++) acc[r][c] = 0ull;

    float4 pa[2], pb[2];
    auto ldT = [&](int kt) {
        const int k0 = kt * 16;
        #pragma unroll
        for (int i = 0; i < 2; i++) {
            int idx = tid + i * 256;
            int r = idx >> 2, kq = (idx & 3) * 4;
            pa[i] = *(const float4*)(Ap + (size_t)(m0 + r) * 512 + k0 + kq);
            pb[i] = *(const float4*)(W  + (size_t)(n0 + r) * 512 + k0 + kq);
        }
    };
    auto stT = [&](int s) {
        #pragma unroll
        for (int i = 0; i < 2; i++) {
            int idx = tid + i * 256;
            int r = idx >> 2, kq = (idx & 3) * 4;
            As[s][kq+0][r] = pa[i].x; As[s][kq+1][r] = pa[i].y;
            As[s][kq+2][r] = pa[i].z; As[s][kq+3][r] = pa[i].w;
            Bs[s][kq+0][r] = pb[i].x; Bs[s][kq+1][r] = pb[i].y;
            Bs[s][kq+2][r] = pb[i].z; Bs[s][kq+3][r] = pb[i].w;
        }
    };

    ldT(0); stT(0); __syncthreads();
    ldT(1);

    for (int kt = 0; kt < 32; kt++) {
        if (kt < 31) stT((kt + 1) & 1);
        if (kt < 30) ldT(kt + 2);
        const int st = kt & 1;
        #pragma unroll
        for (int kk = 0; kk < 16; kk++) {
            float4 ba = *(const float4*)&Bs[st][kk][tx * 4];
            float4 bb = *(const float4*)&Bs[st][kk][64 + tx * 4];
            ull kp0 = pk2(ba.x, ba.y), kp1 = pk2(ba.z, ba.w);
            ull kp2 = pk2(bb.x, bb.y), kp3 = pk2(bb.z, bb.w);
            float4 av0 = *(const float4*)&As[st][kk][ty * 8];
            float4 av1 = *(const float4*)&As[st][kk][ty * 8 + 4];
            float am[8] = {av0.x, av0.y, av0.z, av0.w, av1.x, av1.y, av1.z, av1.w};
            #pragma unroll
            for (int r = 0; r < 8; r++) {
                ull ab = pk2(am[r], am[r]);
                fma2(acc[r][0], ab, kp0); fma2(acc[r][1], ab, kp1);
                fma2(acc[r][2], ab, kp2); fma2(acc[r][3], ab, kp3);
            }
        }
        if (kt < 31) __syncthreads();
    }

    #pragma unroll
    for (int r = 0; r < 8; r++) {
        int m = m0 + ty * 8 + r;
        #pragma unroll
        for (int c = 0; c < 4; c++) {
            int n = n0 + ((c < 2) ? (tx * 4 + 2 * c) : (64 + tx * 4 + 2 * (c - 2)));
            if (MODE == 0) {
                int b = m >> 10, i = m & 1023;
                float2 v = upk(acc[r][c]);
                if (n < 512) {
                    int hh = n >> 6, d = n & 63;
                    float* p = g_q + (((size_t)(b * 8 + hh) << 10) + i) * 64 + d;
                    p[0] = v.x * 0.125f; p[1] = v.y * 0.125f;   // fold attn scale (exact pow2)
                } else if (n < 1024) {
                    int nn = n - 512, hh = nn >> 6, d = nn & 63;
                    float* p = g_kt + ((size_t)(b * 8 + hh) * 64 + d) * 1024 + i;
                    p[0] = v.x; p[1024] = v.y;
                } else {
                    int nn = n - 1024, hh = nn >> 6, d = nn & 63;
                    float* p = g_v + (((size_t)(b * 8 + hh) << 10) + i) * 64 + d;
                    p[0] = v.x; p[1] = v.y;
                }
            } else {
                ull bv = *(const ull*)(bias + n);
                *(ull*)(out + (size_t)m * 512 + n) = add2(acc[r][c], bv);
            }
        }
    }
}

// ======================= K2: pooling + selector (R9-proven) =======================
__global__ void __launch_bounds__(512) pool_kernel(const float* __restrict__ x) {
    const int b = blockIdx.x >> 3, s = blockIdx.x & 7;
    const int tid = threadIdx.x;
    const float* xb = x + ((size_t)b * 1024 + s * 128) * 512;
    float sum = 0.f;
    #pragma unroll 4
    for (int i = 0; i < 128; i++) sum += xb[(size_t)i * 512 + tid];
    g_part[(b * 8 + s) * 512 + tid] = sum;
}

__global__ void __launch_bounds__(512) selector(const float* __restrict__ W1,
                                                const float* __restrict__ b1,
                                                const float* __restrict__ W2,
                                                const float* __restrict__ b2,
                                                const float* __restrict__ logtau) {
    __shared__ float pooled[512];
    __shared__ float hh[256];
    __shared__ float lg[3];
    const int b = blockIdx.x, tid = threadIdx.x;
    {
        float s = 0.f;
        #pragma unroll
        for (int p = 0; p < 8; p++) s += g_part[(b * 8 + p) * 512 + tid];
        pooled[tid] = s * (1.0f / 1024.0f);
    }
    __syncthreads();
    if (tid < 256) {
        float a = b1[tid];
        const float* wr = W1 + (size_t)tid * 512;
        #pragma unroll 4
        for (int d = 0; d < 512; d++) a = fmaf(pooled[d], wr[d], a);
        hh[tid] = a > 0.f ? a : 0.f;
    }
    __syncthreads();
    if (tid < 3) {
        float a = b2[tid];
        const float* wr = W2 + (size_t)tid * 256;
        for (int d = 0; d < 256; d++) a = fmaf(hh[d], wr[d], a);
        lg[tid] = a;
    }
    __syncthreads();
    if (tid == 0) {
        float tau = expf(logtau[0]);
        tau = fminf(fmaxf(tau, 1e-4f), 10.0f);
        float l0 = lg[0] / tau, l1 = lg[1] / tau, l2 = lg[2] / tau;
        float mx = fmaxf(l0, fmaxf(l1, l2));
        float e0 = expf(l0 - mx), e1 = expf(l1 - mx), e2 = expf(l2 - mx);
        float inv = 1.0f / (e0 + e1 + e2);
        g_pw[b * 3 + 0] = e0 * inv;
        g_pw[b * 3 + 1] = e1 * inv;
        g_pw[b * 3 + 2] = e2 * inv;
    }
}

// ======================= K3: score GEMM, whole K=64 resident, 1 barrier (R7-proven) ============
struct SmemSG {
    float4 As4[16][130];   // [kq4][row]: component e = Q[row][kq4*4+e]; 33.3 KB
    float  Bs[64][132];    // [kk][col]; 33.8 KB
};

__global__ void __launch_bounds__(256, 2) scoreg() {
    extern __shared__ char smraw[];
    SmemSG* sm = (SmemSG*)smraw;
    const int bh = blockIdx.z;
    const int m0 = blockIdx.y * 128, n0 = blockIdx.x * 128;
    const int tid = threadIdx.x;
    const int tx = tid & 15, ty = tid >> 4;
    const float* qg  = g_q  + (size_t)bh * 65536;
    const float* ktg = g_kt + (size_t)bh * 65536;

    #pragma unroll
    for (int it = 0; it < 8; it++) {
        int idx = tid + it * 256;
        int row = idx >> 4, kq4 = idx & 15;
        sm->As4[kq4][row] = *(const float4*)(qg + (size_t)(m0 + row) * 64 + kq4 * 4);
    }
    #pragma unroll
    for (int it = 0; it < 8; it++) {
        int idx = tid + it * 256;
        int kk = idx >> 5, c4 = idx & 31;
        *(float4*)&sm->Bs[kk][c4 * 4] = *(const float4*)(ktg + (size_t)kk * 1024 + n0 + c4 * 4);
    }
    __syncthreads();

    ull acc[8][4];
    #pragma unroll
    for (int r = 0; r < 8; r++)
        #pragma unroll
        for (int c = 0; c < 4; c++) acc[r][c] = 0ull;

    #pragma unroll
    for (int kq4 = 0; kq4 < 16; kq4++) {
        float4 a[8];
        #pragma unroll
        for (int r = 0; r < 8; r++) a[r] = sm->As4[kq4][ty * 8 + r];
        #pragma unroll
        for (int e = 0; e < 4; e++) {
            const int kk = kq4 * 4 + e;
            ulonglong2 b0 = *(const ulonglong2*)&sm->Bs[kk][tx * 4];
            ulonglong2 b1 = *(const ulonglong2*)&sm->Bs[kk][64 + tx * 4];
            #pragma unroll
            for (int r = 0; r < 8; r++) {
                float av = (e == 0) ? a[r].x : (e == 1) ? a[r].y : (e == 2) ? a[r].z : a[r].w;
                ull ab = pk2(av, av);
                fma2(acc[r][0], ab, b0.x); fma2(acc[r][1], ab, b0.y);
                fma2(acc[r][2], ab, b1.x); fma2(acc[r][3], ab, b1.y);
            }
        }
    }

    #pragma unroll
    for (int r = 0; r < 8; r++) {
        size_t rowp = ((size_t)bh << 20) + (size_t)(m0 + ty * 8 + r) * 1024;
        float2 v0 = upk(acc[r][0]);
        float2 v1 = upk(acc[r][1]);
        float4 o0 = {v0.x, v0.y, v1.x, v1.y};
        *(float4*)(g_sc + rowp + n0 + tx * 4) = o0;
        float2 v2 = upk(acc[r][2]);
        float2 v3 = upk(acc[r][3]);
        float4 o1 = {v2.x, v2.y, v3.x, v3.y};
        *(float4*)(g_sc + rowp + n0 + 64 + tx * 4) = o1;
    }
}

// ======================= K4: mask + topk + softmax; fast path when smask irrelevant ============
__global__ void __launch_bounds__(512) masksm(const int* __restrict__ mask,
                                              const float* __restrict__ sparse_w,
                                              const float* __restrict__ sparse_b) {
    __shared__ unsigned hist[16][256];
    const int tid = threadIdx.x;
    const int wq = tid >> 5, lane = tid & 31;
    const int i0 = blockIdx.x * 16;
    const int h  = blockIdx.y;
    const int b  = blockIdx.z;
    const int bh = b * 8 + h;
    float* rowp = g_sc + ((size_t)bh << 20) + (size_t)(i0 + wq) * 1024;

    const float pw0 = g_pw[b * 3 + 0], pw1 = g_pw[b * 3 + 1], pw2 = g_pw[b * 3 + 2];
    const float wsp = sparse_w[h], bsp = sparse_b[h];
    const bool need_smask = (((pw1 > 0.05f) != (pw1 + pw2 > 0.05f)) ||
                             ((pw0 + pw1 > 0.05f) != (pw0 + pw1 + pw2 > 0.05f)));

    float4 v[8];
    #pragma unroll
    for (int t = 0; t < 8; t++) v[t] = *(const float4*)(rowp + t * 128 + lane * 4);

    const int* mrow = mask + b * 1024;
    const int ii = i0 + wq;
    float locmax = -3.0e38f;
    int any = 0;

    if (need_smask) {
        unsigned prefix = 0;
        int kneed = KNEED;
        #pragma unroll
        for (int pass = 0; pass < 4; pass++) {
            const int shift = 24 - 8 * pass;
            #pragma unroll
            for (int q = 0; q < 8; q++) hist[wq][lane * 8 + q] = 0u;
            __syncwarp();
            #pragma unroll
            for (int t = 0; t < 8; t++) {
                float fv[4] = {v[t].x, v[t].y, v[t].z, v[t].w};
                #pragma unroll
                for (int e = 0; e < 4; e++) {
                    float s = fmaf(fv[e], wsp, bsp);
                    unsigned u = ordkey(s);
                    bool cand = (pass == 0) || (((u ^ prefix) >> (shift + 8)) == 0u);
                    int bucket = cand ? (int)((u >> shift) & 255u) : 256;
                    unsigned mm = __match_any_sync(0xffffffffu, bucket);
                    if ((__ffs(mm) - 1) == lane && bucket < 256)
                        atomicAdd(&hist[wq][bucket], (unsigned)__popc(mm));
                }
            }
            __syncwarp();
            const int base = 255 - lane * 8;
            int c[8]; int loc = 0;
            #pragma unroll
            for (int q = 0; q < 8; q++) { c[q] = (int)hist[wq][base - q]; loc += c[q]; }
            int pre = loc;
            #pragma unroll
            for (int o = 1; o < 32; o <<= 1) {
                int vv = __shfl_up_sync(0xffffffffu, pre, o);
                if (lane >= o) pre += vv;
            }
            const int excl = pre - loc;
            const bool hit = (excl < kneed) && (kneed <= pre);
            const unsigned hb = __ballot_sync(0xffffffffu, hit);
            const int hl = __ffs(hb) - 1;
            int bsel = 0, kn2 = 0;
            if (hit) {
                int rem = kneed - excl;
                #pragma unroll
                for (int q = 0; q < 8; q++) {
                    if (rem <= c[q]) { bsel = base - q; kn2 = rem; break; }
                    rem -= c[q];
                }
            }
            bsel = __shfl_sync(0xffffffffu, bsel, hl);
            kn2  = __shfl_sync(0xffffffffu, kn2,  hl);
            prefix |= ((unsigned)bsel) << shift;
            kneed = kn2;
            __syncwarp();
        }
        const unsigned thrv = prefix;

        #pragma unroll
        for (int t = 0; t < 8; t++) {
            int4 mm4 = *(const int4*)(mrow + t * 128 + lane * 4);
            float fv[4] = {v[t].x, v[t].y, v[t].z, v[t].w};
            int   mv[4] = {mm4.x, mm4.y, mm4.z, mm4.w};
            #pragma unroll
            for (int e = 0; e < 4; e++) {
                int j = t * 128 + lane * 4 + e;
                float s = fmaf(fv[e], wsp, bsp);
                float smv = (ordkey(s) >= thrv) ? 1.0f : 0.0f;
                float lcl = (j >= ii - 16 && j <= ii + 16) ? 1.0f : 0.0f;
                float comb = fmaf(pw0, lcl, fmaf(pw2, smv, pw1));
                bool keep = (comb > 0.05f) && (mv[e] != 0);
                if (keep) { locmax = fmaxf(locmax, fv[e]); any = 1; }
                else      fv[e] = NEGV;
            }
            v[t].x = fv[0]; v[t].y = fv[1]; v[t].z = fv[2]; v[t].w = fv[3];
        }
    } else {
        // smv == 1 everywhere: keep depends only on window predicate + mask.
        const bool keepW = (pw0 + pw1 + pw2 > 0.05f);   // inside local window
        const bool keepO = (pw1 + pw2 > 0.05f);          // outside window
        #pragma unroll
        for (int t = 0; t < 8; t++) {
            int4 mm4 = *(const int4*)(mrow + t * 128 + lane * 4);
            float fv[4] = {v[t].x, v[t].y, v[t].z, v[t].w};
            int   mv[4] = {mm4.x, mm4.y, mm4.z, mm4.w};
            #pragma unroll
            for (int e = 0; e < 4; e++) {
                int j = t * 128 + lane * 4 + e;
                bool inw = (j >= ii - 16 && j <= ii + 16);
                bool keep = (inw ? keepW : keepO) && (mv[e] != 0);
                if (keep) { locmax = fmaxf(locmax, fv[e]); any = 1; }
                else      fv[e] = NEGV;
            }
            v[t].x = fv[0]; v[t].y = fv[1]; v[t].z = fv[2]; v[t].w = fv[3];
        }
    }

    #pragma unroll
    for (int o = 16; o; o >>= 1) {
        locmax = fmaxf(locmax, __shfl_xor_sync(0xffffffffu, locmax, o));
        any   |= __shfl_xor_sync(0xffffffffu, any, o);
    }
    if (!any) {
        if (lane == 0) v[0].x = 0.0f;    // j==0 fallback
        locmax = 0.0f;
    }

    float lsum = 0.f;
    #pragma unroll
    for (int t = 0; t < 8; t++) {
        v[t].x = __expf(v[t].x - locmax); v[t].y = __expf(v[t].y - locmax);
        v[t].z = __expf(v[t].z - locmax); v[t].w = __expf(v[t].w - locmax);
        lsum += (v[t].x + v[t].y) + (v[t].z + v[t].w);
    }
    #pragma unroll
    for (int o = 16; o; o >>= 1)
        lsum += __shfl_xor_sync(0xffffffffu, lsum, o);
    const float inv = 1.0f / lsum;
    #pragma unroll
    for (int t = 0; t < 8; t++) {
        v[t].x *= inv; v[t].y *= inv; v[t].z *= inv; v[t].w *= inv;
        *(float4*)(rowp + t * 128 + lane * 4) = v[t];
    }
}

// ======================= K5: AV GEMM, 128x64 tile, 256 thr, 2/SM, ratio-4, single-sync =========
__global__ void __launch_bounds__(256, 2) avg_kernel() {
    __shared__ ull   Ps2[2][32][130];  // [kk][row 0..127] dup pairs; 66.6 KB (row 1040B)
    __shared__ float Bs [2][32][68];   // [kk][col]; 17.4 KB
    const int bh = blockIdx.y;
    const int m0 = blockIdx.x * 128;   // grid (8, 32)
    const int tid = threadIdx.x;
    const int tx = tid & 7, ty = tid >> 3;   // ty 0..31: rows ty*4..+4; cols tx*4 and 32+tx*4
    const float* pg = g_sc + ((size_t)bh << 20);
    const float* vg = g_v + (size_t)bh * 65536;

    ull acc[4][4];
    #pragma unroll
    for (int r = 0; r < 4; r++)
        #pragma unroll
        for (int c = 0; c < 4; c++) acc[r][c] = 0ull;

    float4 pr[4], vr[2];
    auto ldT = [&](int c) {
        const int k0 = c * 32;
        #pragma unroll
        for (int it = 0; it < 4; it++) {
            int idx = tid + it * 256;   // 0..1023: 128 rows x 8 k-quads
            pr[it] = *(const float4*)(pg + (size_t)(m0 + (idx >> 3)) * 1024 + k0 + (idx & 7) * 4);
        }
        #pragma unroll
        for (int it = 0; it < 2; it++) {
            int idx = tid + it * 256;   // 0..511: 32 k x 16 col-quads
            vr[it] = *(const float4*)(vg + (size_t)(k0 + (idx >> 4)) * 64 + (idx & 15) * 4);
        }
    };
    auto stT = [&](int s) {
        #pragma unroll
        for (int it = 0; it < 4; it++) {
            int idx = tid + it * 256;
            int row = idx >> 3, kq4 = idx & 7;
            Ps2[s][kq4 * 4 + 0][row] = pk2(pr[it].x, pr[it].x);
            Ps2[s][kq4 * 4 + 1][row] = pk2(pr[it].y, pr[it].y);
            Ps2[s][kq4 * 4 + 2][row] = pk2(pr[it].z, pr[it].z);
            Ps2[s][kq4 * 4 + 3][row] = pk2(pr[it].w, pr[it].w);
        }
        #pragma unroll
        for (int it = 0; it < 2; it++) {
            int idx = tid + it * 256;
            *(float4*)&Bs[s][idx >> 4][(idx & 15) * 4] = vr[it];
        }
    };

    ldT(0); stT(0); __syncthreads();
    ldT(1);

    for (int c = 0; c < 32; c++) {
        if (c < 31) stT((c + 1) & 1);
        if (c < 30) ldT(c + 2);
        const int st = c & 1;
        #pragma unroll
        for (int kk = 0; kk < 32; kk++) {
            ulonglong2 p01 = *(const ulonglong2*)&Ps2[st][kk][ty * 4];
            ulonglong2 p23 = *(const ulonglong2*)&Ps2[st][kk][ty * 4 + 2];
            ulonglong2 b0  = *(const ulonglong2*)&Bs[st][kk][tx * 4];
            ulonglong2 b1  = *(const ulonglong2*)&Bs[st][kk][32 + tx * 4];
            ull p[4] = {p01.x, p01.y, p23.x, p23.y};
            #pragma unroll
            for (int r = 0; r < 4; r++) {
                fma2(acc[r][0], p[r], b0.x); fma2(acc[r][1], p[r], b0.y);
                fma2(acc[r][2], p[r], b1.x); fma2(acc[r][3], p[r], b1.y);
            }
        }
        if (c < 31) __syncthreads();
    }

    const int b = bh >> 3, h = bh & 7;
    #pragma unroll
    for (int r = 0; r < 4; r++) {
        int i = m0 + ty * 4 + r;
        float* op = g_ao + ((size_t)(b * 1024 + i)) * 512 + h * 64;
        float2 c0 = upk(acc[r][0]);
        float2 c1 = upk(acc[r][1]);
        float4 o0 = {c0.x, c0.y, c1.x, c1.y};
        *(float4*)(op + tx * 4) = o0;
        float2 c2 = upk(acc[r][2]);
        float2 c3 = upk(acc[r][3]);
        float4 o1 = {c2.x, c2.y, c3.x, c3.y};
        *(float4*)(op + 32 + tx * 4) = o1;
    }
}

// ======================= launch =======================
extern "C" void kernel_launch(void* const* d_in, const int* in_sizes, int n_in,
                              void* d_out, int out_size) {
    const float* x      = (const float*)d_in[0];
    const int*   mask   = (const int*)  d_in[1];
    const float* Wqkv   = (const float*)d_in[2];
    const float* Wproj  = (const float*)d_in[3];
    const float* bproj  = (const float*)d_in[4];
    const float* Wsel1  = (const float*)d_in[5];
    const float* bsel1  = (const float*)d_in[6];
    const float* Wsel2  = (const float*)d_in[7];
    const float* bsel2  = (const float*)d_in[8];
    const float* logtau = (const float*)d_in[9];
    const float* sw     = (const float*)d_in[10];
    const float* sb     = (const float*)d_in[11];
    float* out = (float*)d_out;

    static int smem_set = 0;
    if (!smem_set) {
        cudaFuncSetAttribute(scoreg, cudaFuncAttributeMaxDynamicSharedMemorySize,
                             (int)sizeof(SmemSG));
        smem_set = 1;
    }

    pool_kernel<<<32, 512>>>(x);
    selector<<<4, 512>>>(Wsel1, bsel1, Wsel2, bsel2, logtau);
    gemm128<0><<<dim3(12, 32), 256>>>(x, Wqkv, nullptr, nullptr);
    scoreg<<<dim3(8, 8, 32), 256, sizeof(SmemSG)>>>();
    masksm<<<dim3(64, 8, 4), 512>>>(mask, sw, sb);
    avg_kernel<<<dim3(8, 32), 256>>>();
    gemm128<1><<<dim3(4, 32), 256>>>(nullptr, Wproj, bproj, out);
}

// round 17
// speedup vs baseline: 1.1641x; 1.0766x over previous
#include <cuda_runtime.h>
#include <cstdint>

#define BB    4
#define LL    1024
#define DIMM  512
#define NH    8
#define HDIM  64
#define KNEED 716          // max(1, int(1024 * 0.7))
#define NEGV  (-1e9f)

typedef unsigned long long ull;

// ---------------- scratch (static device globals; no allocation) ----------------
__device__ float g_q [BB*NH*LL*HDIM];   // (b,h,i,d)   NOTE: pre-scaled by 0.125
__device__ float g_kt[BB*NH*HDIM*LL];   // (b,h,d,j)  transposed K
__device__ float g_v [BB*NH*LL*HDIM];   // (b,h,j,d)
__device__ float g_ao[BB*LL*DIMM];      // (b,i,h*64+d) attention output
__device__ float g_pw[BB*3];            // pattern weights per batch
__device__ float g_part[BB*8*DIMM];     // pooling partials
__device__ float g_sc[BB*NH*LL*LL];     // 134MB normalized-P buffer

// ---------------- f32x2 packed helpers ----------------
__device__ __forceinline__ ull pk2(float a, float b) {
    ull r; asm("mov.b64 %0,{%1,%2};" : "=l"(r) : "f"(a), "f"(b)); return r;
}
__device__ __forceinline__ void fma2(ull& d, ull a, ull b) {
    asm("fma.rn.f32x2 %0, %1, %2, %0;" : "+l"(d) : "l"(a), "l"(b));
}
__device__ __forceinline__ ull mul2(ull a, ull b) {
    ull r; asm("mul.rn.f32x2 %0, %1, %2;" : "=l"(r) : "l"(a), "l"(b)); return r;
}
__device__ __forceinline__ ull add2(ull a, ull b) {
    ull r; asm("add.rn.f32x2 %0, %1, %2;" : "=l"(r) : "l"(a), "l"(b)); return r;
}
__device__ __forceinline__ float2 upk(ull v) {
    float2 r; asm("mov.b64 {%0,%1},%2;" : "=f"(r.x), "=f"(r.y) : "l"(v)); return r;
}
__device__ __forceinline__ unsigned ordkey(float s) {
    unsigned u = __float_as_uint(s);
    return (u & 0x80000000u) ? ~u : (u | 0x80000000u);
}

// ======================= K1: 128x128x16 GEMM, single-sync ping-pong (R9-proven, exact) =========
template<int MODE>
__global__ void __launch_bounds__(256, 2) gemm128(const float* __restrict__ A,
                                                  const float* __restrict__ W,
                                                  const float* __restrict__ bias,
                                                  float* __restrict__ out) {
    __shared__ float As[2][16][132];
    __shared__ float Bs[2][16][132];
    const int m0 = blockIdx.y * 128, n0 = blockIdx.x * 128;
    const int tid = threadIdx.x;
    const int tx = tid & 15, ty = tid >> 4;
    const float* Ap = (MODE == 1) ? g_ao : A;

    ull acc[8][4];
    #pragma unroll
    for (int r = 0; r < 8; r++)
        #pragma unroll
        for (int c = 0; c < 4; c++) acc[r][c] = 0ull;

    float4 pa[2], pb[2];
    auto ldT = [&](int kt) {
        const int k0 = kt * 16;
        #pragma unroll
        for (int i = 0; i < 2; i++) {
            int idx = tid + i * 256;
            int r = idx >> 2, kq = (idx & 3) * 4;
            pa[i] = *(const float4*)(Ap + (size_t)(m0 + r) * 512 + k0 + kq);
            pb[i] = *(const float4*)(W  + (size_t)(n0 + r) * 512 + k0 + kq);
        }
    };
    auto stT = [&](int s) {
        #pragma unroll
        for (int i = 0; i < 2; i++) {
            int idx = tid + i * 256;
            int r = idx >> 2, kq = (idx & 3) * 4;
            As[s][kq+0][r] = pa[i].x; As[s][kq+1][r] = pa[i].y;
            As[s][kq+2][r] = pa[i].z; As[s][kq+3][r] = pa[i].w;
            Bs[s][kq+0][r] = pb[i].x; Bs[s][kq+1][r] = pb[i].y;
            Bs[s][kq+2][r] = pb[i].z; Bs[s][kq+3][r] = pb[i].w;
        }
    };

    ldT(0); stT(0); __syncthreads();
    ldT(1);

    for (int kt = 0; kt < 32; kt++) {
        if (kt < 31) stT((kt + 1) & 1);
        if (kt < 30) ldT(kt + 2);
        const int st = kt & 1;
        #pragma unroll
        for (int kk = 0; kk < 16; kk++) {
            float4 ba = *(const float4*)&Bs[st][kk][tx * 4];
            float4 bb = *(const float4*)&Bs[st][kk][64 + tx * 4];
            ull kp0 = pk2(ba.x, ba.y), kp1 = pk2(ba.z, ba.w);
            ull kp2 = pk2(bb.x, bb.y), kp3 = pk2(bb.z, bb.w);
            float4 av0 = *(const float4*)&As[st][kk][ty * 8];
            float4 av1 = *(const float4*)&As[st][kk][ty * 8 + 4];
            float am[8] = {av0.x, av0.y, av0.z, av0.w, av1.x, av1.y, av1.z, av1.w};
            #pragma unroll
            for (int r = 0; r < 8; r++) {
                ull ab = pk2(am[r], am[r]);
                fma2(acc[r][0], ab, kp0); fma2(acc[r][1], ab, kp1);
                fma2(acc[r][2], ab, kp2); fma2(acc[r][3], ab, kp3);
            }
        }
        if (kt < 31) __syncthreads();
    }

    #pragma unroll
    for (int r = 0; r < 8; r++) {
        int m = m0 + ty * 8 + r;
        #pragma unroll
        for (int c = 0; c < 4; c++) {
            int n = n0 + ((c < 2) ? (tx * 4 + 2 * c) : (64 + tx * 4 + 2 * (c - 2)));
            if (MODE == 0) {
                int b = m >> 10, i = m & 1023;
                float2 v = upk(acc[r][c]);
                if (n < 512) {
                    int hh = n >> 6, d = n & 63;
                    float* p = g_q + (((size_t)(b * 8 + hh) << 10) + i) * 64 + d;
                    p[0] = v.x * 0.125f; p[1] = v.y * 0.125f;   // fold attn scale (exact pow2)
                } else if (n < 1024) {
                    int nn = n - 512, hh = nn >> 6, d = nn & 63;
                    float* p = g_kt + ((size_t)(b * 8 + hh) * 64 + d) * 1024 + i;
                    p[0] = v.x; p[1024] = v.y;
                } else {
                    int nn = n - 1024, hh = nn >> 6, d = nn & 63;
                    float* p = g_v + (((size_t)(b * 8 + hh) << 10) + i) * 64 + d;
                    p[0] = v.x; p[1] = v.y;
                }
            } else {
                ull bv = *(const ull*)(bias + n);
                *(ull*)(out + (size_t)m * 512 + n) = add2(acc[r][c], bv);
            }
        }
    }
}

// ======================= K2: pooling + selector (R9-proven) =======================
__global__ void __launch_bounds__(512) pool_kernel(const float* __restrict__ x) {
    const int b = blockIdx.x >> 3, s = blockIdx.x & 7;
    const int tid = threadIdx.x;
    const float* xb = x + ((size_t)b * 1024 + s * 128) * 512;
    float sum = 0.f;
    #pragma unroll 4
    for (int i = 0; i < 128; i++) sum += xb[(size_t)i * 512 + tid];
    g_part[(b * 8 + s) * 512 + tid] = sum;
}

__global__ void __launch_bounds__(512) selector(const float* __restrict__ W1,
                                                const float* __restrict__ b1,
                                                const float* __restrict__ W2,
                                                const float* __restrict__ b2,
                                                const float* __restrict__ logtau) {
    __shared__ float pooled[512];
    __shared__ float hh[256];
    __shared__ float lg[3];
    const int b = blockIdx.x, tid = threadIdx.x;
    {
        float s = 0.f;
        #pragma unroll
        for (int p = 0; p < 8; p++) s += g_part[(b * 8 + p) * 512 + tid];
        pooled[tid] = s * (1.0f / 1024.0f);
    }
    __syncthreads();
    if (tid < 256) {
        float a = b1[tid];
        const float* wr = W1 + (size_t)tid * 512;
        #pragma unroll 4
        for (int d = 0; d < 512; d++) a = fmaf(pooled[d], wr[d], a);
        hh[tid] = a > 0.f ? a : 0.f;
    }
    __syncthreads();
    if (tid < 3) {
        float a = b2[tid];
        const float* wr = W2 + (size_t)tid * 256;
        for (int d = 0; d < 256; d++) a = fmaf(hh[d], wr[d], a);
        lg[tid] = a;
    }
    __syncthreads();
    if (tid == 0) {
        float tau = expf(logtau[0]);
        tau = fminf(fmaxf(tau, 1e-4f), 10.0f);
        float l0 = lg[0] / tau, l1 = lg[1] / tau, l2 = lg[2] / tau;
        float mx = fmaxf(l0, fmaxf(l1, l2));
        float e0 = expf(l0 - mx), e1 = expf(l1 - mx), e2 = expf(l2 - mx);
        float inv = 1.0f / (e0 + e1 + e2);
        g_pw[b * 3 + 0] = e0 * inv;
        g_pw[b * 3 + 1] = e1 * inv;
        g_pw[b * 3 + 2] = e2 * inv;
    }
}

// ======================= K3: score GEMM, whole K=64 resident, 1 barrier (R7-proven) ============
struct SmemSG {
    float4 As4[16][130];   // [kq4][row]: component e = Q[row][kq4*4+e]; 33.3 KB
    float  Bs[64][132];    // [kk][col]; 33.8 KB
};

__global__ void __launch_bounds__(256, 2) scoreg() {
    extern __shared__ char smraw[];
    SmemSG* sm = (SmemSG*)smraw;
    const int bh = blockIdx.z;
    const int m0 = blockIdx.y * 128, n0 = blockIdx.x * 128;
    const int tid = threadIdx.x;
    const int tx = tid & 15, ty = tid >> 4;
    const float* qg  = g_q  + (size_t)bh * 65536;
    const float* ktg = g_kt + (size_t)bh * 65536;

    #pragma unroll
    for (int it = 0; it < 8; it++) {
        int idx = tid + it * 256;
        int row = idx >> 4, kq4 = idx & 15;
        sm->As4[kq4][row] = *(const float4*)(qg + (size_t)(m0 + row) * 64 + kq4 * 4);
    }
    #pragma unroll
    for (int it = 0; it < 8; it++) {
        int idx = tid + it * 256;
        int kk = idx >> 5, c4 = idx & 31;
        *(float4*)&sm->Bs[kk][c4 * 4] = *(const float4*)(ktg + (size_t)kk * 1024 + n0 + c4 * 4);
    }
    __syncthreads();

    ull acc[8][4];
    #pragma unroll
    for (int r = 0; r < 8; r++)
        #pragma unroll
        for (int c = 0; c < 4; c++) acc[r][c] = 0ull;

    #pragma unroll
    for (int kq4 = 0; kq4 < 16; kq4++) {
        float4 a[8];
        #pragma unroll
        for (int r = 0; r < 8; r++) a[r] = sm->As4[kq4][ty * 8 + r];
        #pragma unroll
        for (int e = 0; e < 4; e++) {
            const int kk = kq4 * 4 + e;
            ulonglong2 b0 = *(const ulonglong2*)&sm->Bs[kk][tx * 4];
            ulonglong2 b1 = *(const ulonglong2*)&sm->Bs[kk][64 + tx * 4];
            #pragma unroll
            for (int r = 0; r < 8; r++) {
                float av = (e == 0) ? a[r].x : (e == 1) ? a[r].y : (e == 2) ? a[r].z : a[r].w;
                ull ab = pk2(av, av);
                fma2(acc[r][0], ab, b0.x); fma2(acc[r][1], ab, b0.y);
                fma2(acc[r][2], ab, b1.x); fma2(acc[r][3], ab, b1.y);
            }
        }
    }

    #pragma unroll
    for (int r = 0; r < 8; r++) {
        size_t rowp = ((size_t)bh << 20) + (size_t)(m0 + ty * 8 + r) * 1024;
        float2 v0 = upk(acc[r][0]);
        float2 v1 = upk(acc[r][1]);
        float4 o0 = {v0.x, v0.y, v1.x, v1.y};
        *(float4*)(g_sc + rowp + n0 + tx * 4) = o0;
        float2 v2 = upk(acc[r][2]);
        float2 v3 = upk(acc[r][3]);
        float4 o1 = {v2.x, v2.y, v3.x, v3.y};
        *(float4*)(g_sc + rowp + n0 + 64 + tx * 4) = o1;
    }
}

// ======================= K4: mask + topk + softmax; fast path when smask irrelevant ============
__global__ void __launch_bounds__(512) masksm(const int* __restrict__ mask,
                                              const float* __restrict__ sparse_w,
                                              const float* __restrict__ sparse_b) {
    __shared__ unsigned hist[16][256];
    const int tid = threadIdx.x;
    const int wq = tid >> 5, lane = tid & 31;
    const int i0 = blockIdx.x * 16;
    const int h  = blockIdx.y;
    const int b  = blockIdx.z;
    const int bh = b * 8 + h;
    float* rowp = g_sc + ((size_t)bh << 20) + (size_t)(i0 + wq) * 1024;

    const float pw0 = g_pw[b * 3 + 0], pw1 = g_pw[b * 3 + 1], pw2 = g_pw[b * 3 + 2];
    const float wsp = sparse_w[h], bsp = sparse_b[h];
    const bool need_smask = (((pw1 > 0.05f) != (pw1 + pw2 > 0.05f)) ||
                             ((pw0 + pw1 > 0.05f) != (pw0 + pw1 + pw2 > 0.05f)));

    float4 v[8];
    #pragma unroll
    for (int t = 0; t < 8; t++) v[t] = *(const float4*)(rowp + t * 128 + lane * 4);

    const int* mrow = mask + b * 1024;
    const int ii = i0 + wq;
    float locmax = -3.0e38f;
    int any = 0;

    if (need_smask) {
        unsigned prefix = 0;
        int kneed = KNEED;
        #pragma unroll
        for (int pass = 0; pass < 4; pass++) {
            const int shift = 24 - 8 * pass;
            #pragma unroll
            for (int q = 0; q < 8; q++) hist[wq][lane * 8 + q] = 0u;
            __syncwarp();
            #pragma unroll
            for (int t = 0; t < 8; t++) {
                float fv[4] = {v[t].x, v[t].y, v[t].z, v[t].w};
                #pragma unroll
                for (int e = 0; e < 4; e++) {
                    float s = fmaf(fv[e], wsp, bsp);
                    unsigned u = ordkey(s);
                    bool cand = (pass == 0) || (((u ^ prefix) >> (shift + 8)) == 0u);
                    int bucket = cand ? (int)((u >> shift) & 255u) : 256;
                    unsigned mm = __match_any_sync(0xffffffffu, bucket);
                    if ((__ffs(mm) - 1) == lane && bucket < 256)
                        atomicAdd(&hist[wq][bucket], (unsigned)__popc(mm));
                }
            }
            __syncwarp();
            const int base = 255 - lane * 8;
            int c[8]; int loc = 0;
            #pragma unroll
            for (int q = 0; q < 8; q++) { c[q] = (int)hist[wq][base - q]; loc += c[q]; }
            int pre = loc;
            #pragma unroll
            for (int o = 1; o < 32; o <<= 1) {
                int vv = __shfl_up_sync(0xffffffffu, pre, o);
                if (lane >= o) pre += vv;
            }
            const int excl = pre - loc;
            const bool hit = (excl < kneed) && (kneed <= pre);
            const unsigned hb = __ballot_sync(0xffffffffu, hit);
            const int hl = __ffs(hb) - 1;
            int bsel = 0, kn2 = 0;
            if (hit) {
                int rem = kneed - excl;
                #pragma unroll
                for (int q = 0; q < 8; q++) {
                    if (rem <= c[q]) { bsel = base - q; kn2 = rem; break; }
                    rem -= c[q];
                }
            }
            bsel = __shfl_sync(0xffffffffu, bsel, hl);
            kn2  = __shfl_sync(0xffffffffu, kn2,  hl);
            prefix |= ((unsigned)bsel) << shift;
            kneed = kn2;
            __syncwarp();
        }
        const unsigned thrv = prefix;

        #pragma unroll
        for (int t = 0; t < 8; t++) {
            int4 mm4 = *(const int4*)(mrow + t * 128 + lane * 4);
            float fv[4] = {v[t].x, v[t].y, v[t].z, v[t].w};
            int   mv[4] = {mm4.x, mm4.y, mm4.z, mm4.w};
            #pragma unroll
            for (int e = 0; e < 4; e++) {
                int j = t * 128 + lane * 4 + e;
                float s = fmaf(fv[e], wsp, bsp);
                float smv = (ordkey(s) >= thrv) ? 1.0f : 0.0f;
                float lcl = (j >= ii - 16 && j <= ii + 16) ? 1.0f : 0.0f;
                float comb = fmaf(pw0, lcl, fmaf(pw2, smv, pw1));
                bool keep = (comb > 0.05f) && (mv[e] != 0);
                if (keep) { locmax = fmaxf(locmax, fv[e]); any = 1; }
                else      fv[e] = NEGV;
            }
            v[t].x = fv[0]; v[t].y = fv[1]; v[t].z = fv[2]; v[t].w = fv[3];
        }
    } else {
        // smv == 1 everywhere: keep depends only on window predicate + mask.
        const bool keepW = (pw0 + pw1 + pw2 > 0.05f);   // inside local window
        const bool keepO = (pw1 + pw2 > 0.05f);          // outside window
        #pragma unroll
        for (int t = 0; t < 8; t++) {
            int4 mm4 = *(const int4*)(mrow + t * 128 + lane * 4);
            float fv[4] = {v[t].x, v[t].y, v[t].z, v[t].w};
            int   mv[4] = {mm4.x, mm4.y, mm4.z, mm4.w};
            #pragma unroll
            for (int e = 0; e < 4; e++) {
                int j = t * 128 + lane * 4 + e;
                bool inw = (j >= ii - 16 && j <= ii + 16);
                bool keep = (inw ? keepW : keepO) && (mv[e] != 0);
                if (keep) { locmax = fmaxf(locmax, fv[e]); any = 1; }
                else      fv[e] = NEGV;
            }
            v[t].x = fv[0]; v[t].y = fv[1]; v[t].z = fv[2]; v[t].w = fv[3];
        }
    }

    #pragma unroll
    for (int o = 16; o; o >>= 1) {
        locmax = fmaxf(locmax, __shfl_xor_sync(0xffffffffu, locmax, o));
        any   |= __shfl_xor_sync(0xffffffffu, any, o);
    }
    if (!any) {
        if (lane == 0) v[0].x = 0.0f;    // j==0 fallback
        locmax = 0.0f;
    }

    float lsum = 0.f;
    #pragma unroll
    for (int t = 0; t < 8; t++) {
        v[t].x = __expf(v[t].x - locmax); v[t].y = __expf(v[t].y - locmax);
        v[t].z = __expf(v[t].z - locmax); v[t].w = __expf(v[t].w - locmax);
        lsum += (v[t].x + v[t].y) + (v[t].z + v[t].w);
    }
    #pragma unroll
    for (int o = 16; o; o >>= 1)
        lsum += __shfl_xor_sync(0xffffffffu, lsum, o);
    const float inv = 1.0f / lsum;
    #pragma unroll
    for (int t = 0; t < 8; t++) {
        v[t].x *= inv; v[t].y *= inv; v[t].z *= inv; v[t].w *= inv;
        *(float4*)(rowp + t * 128 + lane * 4) = v[t];
    }
}

// ======================= K5: AV GEMM v3 — plain-P smem (scoreg recipe), 128x64 tile =============
__global__ void __launch_bounds__(256, 2) avg_kernel() {
    __shared__ float Ps[2][128][36];   // [row][k], row 144B (16B mult); 36.9 KB
    __shared__ float Bs[2][32][68];    // [k][col]; 17.4 KB
    const int bh = blockIdx.y;
    const int m0 = blockIdx.x * 128;   // grid (8, 32)
    const int tid = threadIdx.x;
    const int tx = tid & 7, ty = tid >> 3;   // ty 0..31: rows ty*4..+4; cols tx*4 and 32+tx*4
    const float* pg = g_sc + ((size_t)bh << 20);
    const float* vg = g_v + (size_t)bh * 65536;

    ull acc[4][4];
    #pragma unroll
    for (int r = 0; r < 4; r++)
        #pragma unroll
        for (int c = 0; c < 4; c++) acc[r][c] = 0ull;

    float4 pr[4], vr[2];
    auto ldT = [&](int c) {
        const int k0 = c * 32;
        #pragma unroll
        for (int it = 0; it < 4; it++) {
            int idx = tid + it * 256;   // 0..1023: 128 rows x 8 k-quads
            pr[it] = *(const float4*)(pg + (size_t)(m0 + (idx >> 3)) * 1024 + k0 + (idx & 7) * 4);
        }
        #pragma unroll
        for (int it = 0; it < 2; it++) {
            int idx = tid + it * 256;   // 0..511: 32 k x 16 col-quads
            vr[it] = *(const float4*)(vg + (size_t)(k0 + (idx >> 4)) * 64 + (idx & 15) * 4);
        }
    };
    auto stT = [&](int s) {
        #pragma unroll
        for (int it = 0; it < 4; it++) {
            int idx = tid + it * 256;
            *(float4*)&Ps[s][idx >> 3][(idx & 7) * 4] = pr[it];   // direct copy, no dup
        }
        #pragma unroll
        for (int it = 0; it < 2; it++) {
            int idx = tid + it * 256;
            *(float4*)&Bs[s][idx >> 4][(idx & 15) * 4] = vr[it];
        }
    };

    ldT(0); stT(0); __syncthreads();
    ldT(1);

    for (int c = 0; c < 32; c++) {
        if (c < 31) stT((c + 1) & 1);
        if (c < 30) ldT(c + 2);
        const int st = c & 1;
        #pragma unroll
        for (int kkq = 0; kkq < 8; kkq++) {
            float4 pv[4];
            #pragma unroll
            for (int r = 0; r < 4; r++)
                pv[r] = *(const float4*)&Ps[st][ty * 4 + r][kkq * 4];
            #pragma unroll
            for (int e = 0; e < 4; e++) {
                const int kk = kkq * 4 + e;
                ulonglong2 b0 = *(const ulonglong2*)&Bs[st][kk][tx * 4];
                ulonglong2 b1 = *(const ulonglong2*)&Bs[st][kk][32 + tx * 4];
                #pragma unroll
                for (int r = 0; r < 4; r++) {
                    float pe = (e == 0) ? pv[r].x : (e == 1) ? pv[r].y : (e == 2) ? pv[r].z : pv[r].w;
                    ull pb = pk2(pe, pe);
                    fma2(acc[r][0], pb, b0.x); fma2(acc[r][1], pb, b0.y);
                    fma2(acc[r][2], pb, b1.x); fma2(acc[r][3], pb, b1.y);
                }
            }
        }
        if (c < 31) __syncthreads();
    }

    const int b = bh >> 3, h = bh & 7;
    #pragma unroll
    for (int r = 0; r < 4; r++) {
        int i = m0 + ty * 4 + r;
        float* op = g_ao + ((size_t)(b * 1024 + i)) * 512 + h * 64;
        float2 c0 = upk(acc[r][0]);
        float2 c1 = upk(acc[r][1]);
        float4 o0 = {c0.x, c0.y, c1.x, c1.y};
        *(float4*)(op + tx * 4) = o0;
        float2 c2 = upk(acc[r][2]);
        float2 c3 = upk(acc[r][3]);
        float4 o1 = {c2.x, c2.y, c3.x, c3.y};
        *(float4*)(op + 32 + tx * 4) = o1;
    }
}

// ======================= launch =======================
extern "C" void kernel_launch(void* const* d_in, const int* in_sizes, int n_in,
                              void* d_out, int out_size) {
    const float* x      = (const float*)d_in[0];
    const int*   mask   = (const int*)  d_in[1];
    const float* Wqkv   = (const float*)d_in[2];
    const float* Wproj  = (const float*)d_in[3];
    const float* bproj  = (const float*)d_in[4];
    const float* Wsel1  = (const float*)d_in[5];
    const float* bsel1  = (const float*)d_in[6];
    const float* Wsel2  = (const float*)d_in[7];
    const float* bsel2  = (const float*)d_in[8];
    const float* logtau = (const float*)d_in[9];
    const float* sw     = (const float*)d_in[10];
    const float* sb     = (const float*)d_in[11];
    float* out = (float*)d_out;

    static int smem_set = 0;
    if (!smem_set) {
        cudaFuncSetAttribute(scoreg, cudaFuncAttributeMaxDynamicSharedMemorySize,
                             (int)sizeof(SmemSG));
        smem_set = 1;
    }

    pool_kernel<<<32, 512>>>(x);
    selector<<<4, 512>>>(Wsel1, bsel1, Wsel2, bsel2, logtau);
    gemm128<0><<<dim3(12, 32), 256>>>(x, Wqkv, nullptr, nullptr);
    scoreg<<<dim3(8, 8, 32), 256, sizeof(SmemSG)>>>();
    masksm<<<dim3(64, 8, 4), 512>>>(mask, sw, sb);
    avg_kernel<<<dim3(8, 32), 256>>>();
    gemm128<1><<<dim3(4, 32), 256>>>(nullptr, Wproj, bproj, out);
}